// round 1
// baseline (speedup 1.0000x reference)
#include <cuda_runtime.h>
#include <math.h>

#define S_LEN  4096
#define D_MODEL 1024
#define NH     16
#define DKH    64
#define FF     4096

// ---------------- scratch (device globals: no allocation allowed) ----------
__device__ float g_q[NH * S_LEN * DKH];
__device__ float g_k[NH * S_LEN * DKH];
__device__ float g_v[NH * S_LEN * DKH];
__device__ float g_concat[S_LEN * D_MODEL];
__device__ float g_tmp[S_LEN * D_MODEL];     // attn_out, then ffn_out
__device__ float g_x1[S_LEN * D_MODEL];
__device__ float g_h1[S_LEN * FF];

// ---------------- generic 64x64x16 register-tiled SGEMM --------------------
// C[m][n] = sum_k A[m][k] * B[k][n] + bias[n], optional ReLU.
// A: row-major [M,K]; B: row-major [K,N] (+ z*bStride); C row-major (+ z*cStride).
// All dims are multiples of the tile sizes (no bounds checks needed).
template <bool RELU>
__global__ void sgemm_kernel(const float* __restrict__ A,
                             const float* __restrict__ B,
                             const float* __restrict__ bias,
                             float* __restrict__ C,
                             int K, int N,
                             long bStride, long biasStride, long cStride)
{
    __shared__ float As[16][68];
    __shared__ float Bs[16][68];

    const int t  = threadIdx.x;        // 256 threads
    const int tx = t & 15;
    const int ty = t >> 4;
    const int m0 = blockIdx.y * 64;
    const int n0 = blockIdx.x * 64;

    const float* Ab = A + (long)m0 * K;
    const float* Bb = B + (long)blockIdx.z * bStride + n0;
    const float* bb = bias + (long)blockIdx.z * biasStride + n0;
    float* Cb = C + (long)blockIdx.z * cStride;

    // A-load indices: thread loads one float4 (row t>>2, k-quad t&3)
    const int arow = t >> 2;
    const int akq  = t & 3;
    // B-load indices: thread loads 4 scalars (col t&63, k rows t>>6 + 4j)
    const int bn = t & 63;
    const int bk = t >> 6;

    float acc[4][4];
#pragma unroll
    for (int i = 0; i < 4; i++)
#pragma unroll
        for (int j = 0; j < 4; j++) acc[i][j] = 0.f;

    for (int k0 = 0; k0 < K; k0 += 16) {
        float4 av = *(const float4*)&Ab[(long)arow * K + k0 + akq * 4];
        As[akq * 4 + 0][arow] = av.x;
        As[akq * 4 + 1][arow] = av.y;
        As[akq * 4 + 2][arow] = av.z;
        As[akq * 4 + 3][arow] = av.w;
#pragma unroll
        for (int j = 0; j < 4; j++)
            Bs[bk + j * 4][bn] = Bb[(long)(k0 + bk + j * 4) * N + bn];
        __syncthreads();

#pragma unroll
        for (int kk = 0; kk < 16; kk++) {
            float4 a = *(const float4*)&As[kk][ty * 4];
            float4 b = *(const float4*)&Bs[kk][tx * 4];
            acc[0][0] += a.x * b.x; acc[0][1] += a.x * b.y; acc[0][2] += a.x * b.z; acc[0][3] += a.x * b.w;
            acc[1][0] += a.y * b.x; acc[1][1] += a.y * b.y; acc[1][2] += a.y * b.z; acc[1][3] += a.y * b.w;
            acc[2][0] += a.z * b.x; acc[2][1] += a.z * b.y; acc[2][2] += a.z * b.z; acc[2][3] += a.z * b.w;
            acc[3][0] += a.w * b.x; acc[3][1] += a.w * b.y; acc[3][2] += a.w * b.z; acc[3][3] += a.w * b.w;
        }
        __syncthreads();
    }

    float4 bi = *(const float4*)&bb[tx * 4];
#pragma unroll
    for (int i = 0; i < 4; i++) {
        const int row = m0 + ty * 4 + i;
        float4 o;
        o.x = acc[i][0] + bi.x;
        o.y = acc[i][1] + bi.y;
        o.z = acc[i][2] + bi.z;
        o.w = acc[i][3] + bi.w;
        if (RELU) {
            o.x = fmaxf(o.x, 0.f); o.y = fmaxf(o.y, 0.f);
            o.z = fmaxf(o.z, 0.f); o.w = fmaxf(o.w, 0.f);
        }
        *(float4*)&Cb[(long)row * N + n0 + tx * 4] = o;
    }
}

// ---------------- flash attention (fp32, 64x64 tiles, online softmax) ------
// grid: (S/64, H), block 256. Reads g_q/g_k/g_v, writes g_concat[s][h*64+d].
__global__ void flash_attn_kernel()
{
    extern __shared__ float sm[];
    float* Qs   = sm;                 // [64][68], Qs[d][r]  (transposed, pre-scaled)
    float* Ks   = Qs + 64 * 68;       // [64][68], Ks[d][c]  (transposed)
    float* Vs   = Ks + 64 * 68;       // [64][68], Vs[c][d]
    float* Pt   = Vs + 64 * 68;       // [64][68], Pt[c][r]  (scores, transposed)
    float* mrow = Pt + 64 * 68;       // [64]
    float* lrow = mrow + 64;          // [64]
    float* arow = lrow + 64;          // [64]

    const int h  = blockIdx.y;
    const int qb = blockIdx.x * 64;
    const int t  = threadIdx.x;
    const int tx = t & 15;
    const int ty = t >> 4;

    const float* Qg = g_q + ((long)h * S_LEN + qb) * DKH;
    const float* Kg = g_k + (long)h * S_LEN * DKH;
    const float* Vg = g_v + (long)h * S_LEN * DKH;

    const int ld = t & 63;   // dk index for loads
    const int lc = t >> 6;   // base row

    // load Q tile transposed, folded 1/sqrt(DK)=0.125 scale
#pragma unroll
    for (int j = 0; j < 16; j++) {
        const int r = lc + j * 4;
        Qs[ld * 68 + r] = Qg[(long)r * DKH + ld] * 0.125f;
    }
    if (t < 64) { mrow[t] = -1e30f; lrow[t] = 0.f; }

    float acc[4][4];
#pragma unroll
    for (int i = 0; i < 4; i++)
#pragma unroll
        for (int j = 0; j < 4; j++) acc[i][j] = 0.f;

    __syncthreads();

    for (int kt = 0; kt < S_LEN / 64; kt++) {
        const float* Kt = Kg + (long)kt * 64 * DKH;
        const float* Vt = Vg + (long)kt * 64 * DKH;
#pragma unroll
        for (int j = 0; j < 16; j++) {
            const int c = lc + j * 4;
            Ks[ld * 68 + c] = Kt[(long)c * DKH + ld];
            Vs[c * 68 + ld] = Vt[(long)c * DKH + ld];
        }
        __syncthreads();

        // scores s[r][c] = sum_d Qs[d][r] * Ks[d][c]
        float s[4][4];
#pragma unroll
        for (int i = 0; i < 4; i++)
#pragma unroll
            for (int j = 0; j < 4; j++) s[i][j] = 0.f;
#pragma unroll
        for (int dd = 0; dd < 64; dd++) {
            float4 q4 = *(const float4*)&Qs[dd * 68 + ty * 4];
            float4 k4 = *(const float4*)&Ks[dd * 68 + tx * 4];
            s[0][0] += q4.x * k4.x; s[0][1] += q4.x * k4.y; s[0][2] += q4.x * k4.z; s[0][3] += q4.x * k4.w;
            s[1][0] += q4.y * k4.x; s[1][1] += q4.y * k4.y; s[1][2] += q4.y * k4.z; s[1][3] += q4.y * k4.w;
            s[2][0] += q4.z * k4.x; s[2][1] += q4.z * k4.y; s[2][2] += q4.z * k4.z; s[2][3] += q4.z * k4.w;
            s[3][0] += q4.w * k4.x; s[3][1] += q4.w * k4.y; s[3][2] += q4.w * k4.z; s[3][3] += q4.w * k4.w;
        }
#pragma unroll
        for (int j = 0; j < 4; j++) {
            float4 v;
            v.x = s[0][j]; v.y = s[1][j]; v.z = s[2][j]; v.w = s[3][j];
            *(float4*)&Pt[(tx * 4 + j) * 68 + ty * 4] = v;
        }
        __syncthreads();

        // online softmax: 4 threads per row (row = t>>2, chunk = t&3)
        {
            const int r = t >> 2;
            const int g = t & 3;
            float mx = -1e30f;
#pragma unroll
            for (int j = 0; j < 16; j++)
                mx = fmaxf(mx, Pt[(g * 16 + j) * 68 + r]);
            mx = fmaxf(mx, __shfl_xor_sync(0xffffffffu, mx, 1));
            mx = fmaxf(mx, __shfl_xor_sync(0xffffffffu, mx, 2));
            const float mold = mrow[r];
            const float mnew = fmaxf(mold, mx);
            float sum = 0.f;
#pragma unroll
            for (int j = 0; j < 16; j++) {
                const int c = g * 16 + j;
                const float p = __expf(Pt[c * 68 + r] - mnew);
                Pt[c * 68 + r] = p;
                sum += p;
            }
            sum += __shfl_xor_sync(0xffffffffu, sum, 1);
            sum += __shfl_xor_sync(0xffffffffu, sum, 2);
            if (g == 0) {
                const float al = __expf(mold - mnew);
                mrow[r] = mnew;
                lrow[r] = lrow[r] * al + sum;
                arow[r] = al;
            }
        }
        __syncthreads();

        // O = O*alpha + P @ V
        float al[4];
#pragma unroll
        for (int i = 0; i < 4; i++) al[i] = arow[ty * 4 + i];
#pragma unroll
        for (int i = 0; i < 4; i++)
#pragma unroll
            for (int j = 0; j < 4; j++) acc[i][j] *= al[i];
#pragma unroll
        for (int c = 0; c < 64; c++) {
            float4 p4 = *(const float4*)&Pt[c * 68 + ty * 4];
            float4 v4 = *(const float4*)&Vs[c * 68 + tx * 4];
            acc[0][0] += p4.x * v4.x; acc[0][1] += p4.x * v4.y; acc[0][2] += p4.x * v4.z; acc[0][3] += p4.x * v4.w;
            acc[1][0] += p4.y * v4.x; acc[1][1] += p4.y * v4.y; acc[1][2] += p4.y * v4.z; acc[1][3] += p4.y * v4.w;
            acc[2][0] += p4.z * v4.x; acc[2][1] += p4.z * v4.y; acc[2][2] += p4.z * v4.z; acc[2][3] += p4.z * v4.w;
            acc[3][0] += p4.w * v4.x; acc[3][1] += p4.w * v4.y; acc[3][2] += p4.w * v4.z; acc[3][3] += p4.w * v4.w;
        }
        __syncthreads();
    }

    // epilogue: divide by l, write concat[s][h*64+d]
#pragma unroll
    for (int i = 0; i < 4; i++) {
        const int r = ty * 4 + i;
        const float inv = 1.f / lrow[r];
        float4 o;
        o.x = acc[i][0] * inv; o.y = acc[i][1] * inv;
        o.z = acc[i][2] * inv; o.w = acc[i][3] * inv;
        *(float4*)&g_concat[(long)(qb + r) * (NH * DKH) + h * DKH + tx * 4] = o;
    }
}

// ---------------- layernorm with residual: out = LN(a + b) -----------------
__global__ void ln_residual_kernel(const float* __restrict__ a,
                                   const float* __restrict__ b,
                                   const float* __restrict__ gw,
                                   const float* __restrict__ bw,
                                   float* __restrict__ out)
{
    const int row = blockIdx.x;
    const int t = threadIdx.x;  // 256 threads, D=1024 -> 4 per thread
    const float* ar = a + (long)row * D_MODEL;
    const float* br = b + (long)row * D_MODEL;

    float v[4];
    float s1 = 0.f, s2 = 0.f;
#pragma unroll
    for (int i = 0; i < 4; i++) {
        const int c = t + i * 256;
        const float x = ar[c] + br[c];
        v[i] = x;
        s1 += x;
        s2 += x * x;
    }
#pragma unroll
    for (int o = 16; o; o >>= 1) {
        s1 += __shfl_xor_sync(0xffffffffu, s1, o);
        s2 += __shfl_xor_sync(0xffffffffu, s2, o);
    }
    __shared__ float r1[8], r2[8];
    __shared__ float mu_s, rs_s;
    if ((t & 31) == 0) { r1[t >> 5] = s1; r2[t >> 5] = s2; }
    __syncthreads();
    if (t == 0) {
        float a1 = 0.f, a2 = 0.f;
#pragma unroll
        for (int i = 0; i < 8; i++) { a1 += r1[i]; a2 += r2[i]; }
        const float mu = a1 * (1.f / D_MODEL);
        const float var = a2 * (1.f / D_MODEL) - mu * mu;
        mu_s = mu;
        rs_s = rsqrtf(var + 1e-5f);
    }
    __syncthreads();
    const float mu = mu_s, rs = rs_s;
    float* orow = out + (long)row * D_MODEL;
#pragma unroll
    for (int i = 0; i < 4; i++) {
        const int c = t + i * 256;
        orow[c] = (v[i] - mu) * rs * gw[c] + bw[c];
    }
}

// ---------------- launch ----------------------------------------------------
extern "C" void kernel_launch(void* const* d_in, const int* in_sizes, int n_in,
                              void* d_out, int out_size)
{
    (void)in_sizes; (void)n_in; (void)out_size;
    const float* src   = (const float*)d_in[0];
    const float* Wq    = (const float*)d_in[1];
    const float* bq    = (const float*)d_in[2];
    const float* Wk    = (const float*)d_in[3];
    const float* bk    = (const float*)d_in[4];
    const float* Wv    = (const float*)d_in[5];
    const float* bv    = (const float*)d_in[6];
    const float* Wo    = (const float*)d_in[7];
    const float* bo    = (const float*)d_in[8];
    const float* ln1_g = (const float*)d_in[9];
    const float* ln1_b = (const float*)d_in[10];
    const float* W1    = (const float*)d_in[11];
    const float* b1    = (const float*)d_in[12];
    const float* W2    = (const float*)d_in[13];
    const float* b2    = (const float*)d_in[14];
    const float* ln2_g = (const float*)d_in[15];
    const float* ln2_b = (const float*)d_in[16];
    float* out = (float*)d_out;

    void *pq, *pk, *pv, *pcc, *ptmp, *px1, *ph1;
    cudaGetSymbolAddress(&pq,  g_q);
    cudaGetSymbolAddress(&pk,  g_k);
    cudaGetSymbolAddress(&pv,  g_v);
    cudaGetSymbolAddress(&pcc, g_concat);
    cudaGetSymbolAddress(&ptmp, g_tmp);
    cudaGetSymbolAddress(&px1, g_x1);
    cudaGetSymbolAddress(&ph1, g_h1);

    const int FLASH_SMEM = (4 * 64 * 68 + 3 * 64) * (int)sizeof(float);  // 70400
    cudaFuncSetAttribute(flash_attn_kernel,
                         cudaFuncAttributeMaxDynamicSharedMemorySize, FLASH_SMEM);

    // QKV projections: per-head [4096,1024]x[1024,64], batched over z=H
    const long wStride = (long)D_MODEL * DKH;   // per-head weight stride
    const long cStride = (long)S_LEN * DKH;     // per-head output stride
    sgemm_kernel<false><<<dim3(1, 64, NH), 256>>>(src, Wq, bq, (float*)pq,
                                                  D_MODEL, DKH, wStride, DKH, cStride);
    sgemm_kernel<false><<<dim3(1, 64, NH), 256>>>(src, Wk, bk, (float*)pk,
                                                  D_MODEL, DKH, wStride, DKH, cStride);
    sgemm_kernel<false><<<dim3(1, 64, NH), 256>>>(src, Wv, bv, (float*)pv,
                                                  D_MODEL, DKH, wStride, DKH, cStride);

    // attention -> g_concat [S, H*DK]
    flash_attn_kernel<<<dim3(S_LEN / 64, NH), 256, FLASH_SMEM>>>();

    // output projection: [4096,1024]x[1024,1024]
    sgemm_kernel<false><<<dim3(D_MODEL / 64, 64, 1), 256>>>((const float*)pcc, Wo, bo,
                                                            (float*)ptmp, D_MODEL, D_MODEL, 0, 0, 0);
    // x1 = LN(src + attn_out)
    ln_residual_kernel<<<S_LEN, 256>>>(src, (const float*)ptmp, ln1_g, ln1_b, (float*)px1);

    // FFN up: relu(x1 @ W1 + b1) : [4096,1024]x[1024,4096]
    sgemm_kernel<true><<<dim3(FF / 64, 64, 1), 256>>>((const float*)px1, W1, b1,
                                                      (float*)ph1, D_MODEL, FF, 0, 0, 0);
    // FFN down: h1 @ W2 + b2 : [4096,4096]x[4096,1024]
    sgemm_kernel<false><<<dim3(D_MODEL / 64, 64, 1), 256>>>((const float*)ph1, W2, b2,
                                                            (float*)ptmp, FF, D_MODEL, 0, 0, 0);
    // out = LN(x1 + ffn)
    ln_residual_kernel<<<S_LEN, 256>>>((const float*)px1, (const float*)ptmp, ln2_g, ln2_b, out);
}